// round 15
// baseline (speedup 1.0000x reference)
#include <cuda_runtime.h>
#include <cuda_fp16.h>
#include <cstdint>

#define T_TOK    16384
#define DIM      2048
#define NEXP     64
#define NB       4
#define SEQ      4096
#define BM       64              // tokens per CTA
#define BK       32              // k per chunk (2 x k16 blocks)
#define NCHUNK   (DIM / BK)      // 64
#define NTHREADS 256
#define GRID     (T_TOK / BM)    // 256
#define NKB      (DIM / 16)      // 128 k16-blocks

#define WSCALE   1024.0f         // exact pow2: W residual -> fp16 normal range
#define XSCALE   256.0f          // exact pow2: X residual -> fp16 normal range
#define UNSCALE  (1.0f / (WSCALE * XSCALE))   // 2^-18, exact

// smem: W stages 2 x 8192 B during loop; epilogue red[128][68] f32 = 34816 B
#define WSTAGE_B 8192
#define SMEM_BYTES 34816

// Pre-split W (scaled) in fragment-native layout: [kb][e][tg] -> 16B block
__device__ uint4    g_wfrag[NKB * NEXP * 4];      // 512 KB
__device__ float    g_score_sum[NB * NEXP];
__device__ unsigned g_counts[NB * NEXP];
__device__ unsigned g_done;

__device__ __forceinline__ void split_pair(float x0, float x1,
                                           uint32_t& p1, uint32_t& p2) {
    __half2 h1 = __floats2half2_rn(x0, x1);
    float2  f  = __half22float2(h1);
    __half2 h2 = __floats2half2_rn(x0 - f.x, x1 - f.y);
    p1 = *reinterpret_cast<uint32_t*>(&h1);
    p2 = *reinterpret_cast<uint32_t*>(&h2);
}

__device__ __forceinline__ void mma_f16(float* c,
                                        uint32_t a0, uint32_t a1, uint32_t a2, uint32_t a3,
                                        uint32_t b0, uint32_t b1) {
    asm volatile(
        "mma.sync.aligned.m16n8k16.row.col.f32.f16.f16.f32 "
        "{%0,%1,%2,%3}, {%4,%5,%6,%7}, {%8,%9}, {%0,%1,%2,%3};"
        : "+f"(c[0]), "+f"(c[1]), "+f"(c[2]), "+f"(c[3])
        : "r"(a0), "r"(a1), "r"(a2), "r"(a3), "r"(b0), "r"(b1));
}

__device__ __forceinline__ uint32_t smem_u32(const void* p) {
    uint32_t a;
    asm("{ .reg .u64 t; cvta.to.shared.u64 t, %1; cvt.u32.u64 %0, t; }" : "=r"(a) : "l"(p));
    return a;
}

#define CP_ASYNC16(dst_u32, src_ptr) \
    asm volatile("cp.async.cg.shared.global [%0], [%1], 16;" :: "r"(dst_u32), "l"(src_ptr) : "memory")
#define CP_COMMIT()  asm volatile("cp.async.commit_group;" ::: "memory")
#define CP_WAIT0()   asm volatile("cp.async.wait_group 0;" ::: "memory")

// ---- pre-kernel: split scaled W once into fragment-native layout ----
__global__ void presplit_w_kernel(const float* __restrict__ W) {
    int idx = blockIdx.x * 256 + threadIdx.x;     // 0..32767
    int tg = idx & 3;
    int e  = (idx >> 2) & 63;
    int kb = idx >> 8;
    const float* src = W + (size_t)e * DIM + kb * 16;
    float2 lo = *(const float2*)(src + 2 * tg);
    float2 hi = *(const float2*)(src + 2 * tg + 8);
    uint32_t w0, w1, w2, w3;
    split_pair(lo.x * WSCALE, lo.y * WSCALE, w0, w2);
    split_pair(hi.x * WSCALE, hi.y * WSCALE, w1, w3);
    g_wfrag[idx] = make_uint4(w0, w1, w2, w3);
}

__global__ __launch_bounds__(NTHREADS, 3)
void moe_gate_f16(const float* __restrict__ X,
                  float* __restrict__ out)
{
    extern __shared__ char smem[];
    __shared__ unsigned int cnt[NEXP];
    __shared__ int last_flag;

    const int tid  = threadIdx.x;
    const int wid  = tid >> 5;
    const int lane = tid & 31;
    const int g    = lane >> 2;       // 0..7
    const int tg   = lane & 3;        // 0..3
    const int tgp  = wid >> 1;        // token group 0..3 (16 tokens each)
    const int ksl  = wid & 1;         // k16-slice within k32 chunk
    const int tok0 = blockIdx.x * BM;
    const int row0 = tgp * 16 + g;

    const float* Xr0 = X + (size_t)(tok0 + row0) * DIM + ksl * 16 + 2 * tg;
    const float* Xr1 = Xr0 + 8 * DIM;

    // smem addresses for this thread's two cp.async targets (stage-relative)
    const uint32_t smem_base = smem_u32(smem);
    const uint32_t wdst0 = smem_base + tid * 16;
    const uint32_t wdst1 = smem_base + (tid + 256) * 16;
    const int boff = ksl * 4096 + g * 64 + tg * 16;   // consumer offset (bytes)

    float acc[8][4];
#pragma unroll
    for (int nt = 0; nt < 8; nt++)
#pragma unroll
        for (int i = 0; i < 4; i++) acc[nt][i] = 0.0f;

    // ---- prolog: W chunk 0 via cp.async, X chunk 0 via LDG ----
    CP_ASYNC16(wdst0, &g_wfrag[tid]);
    CP_ASYNC16(wdst1, &g_wfrag[tid + 256]);
    CP_COMMIT();
    float2 ra0 = *(const float2*)(Xr0);
    float2 ra2 = *(const float2*)(Xr0 + 8);
    float2 ra1 = *(const float2*)(Xr1);
    float2 ra3 = *(const float2*)(Xr1 + 8);
    if (tid < NEXP) cnt[tid] = 0u;
    CP_WAIT0();
    __syncthreads();

    for (int kt = 0; kt < NCHUNK; kt++) {
        const int stage = kt & 1;

        // ---- issue W cp.async for next chunk into other stage ----
        if (kt + 1 < NCHUNK) {
            const uint32_t soff = (stage ^ 1) * WSTAGE_B;
            CP_ASYNC16(wdst0 + soff, &g_wfrag[(kt + 1) * 512 + tid]);
            CP_ASYNC16(wdst1 + soff, &g_wfrag[(kt + 1) * 512 + tid + 256]);
            CP_COMMIT();
        }

        // split current (scaled) A into fragments
        uint32_t ah1[4], ah2[4];
        split_pair(ra0.x * XSCALE, ra0.y * XSCALE, ah1[0], ah2[0]);
        split_pair(ra1.x * XSCALE, ra1.y * XSCALE, ah1[1], ah2[1]);
        split_pair(ra2.x * XSCALE, ra2.y * XSCALE, ah1[2], ah2[2]);
        split_pair(ra3.x * XSCALE, ra3.y * XSCALE, ah1[3], ah2[3]);

        // prefetch next X into regs (overlaps MMA)
        if (kt + 1 < NCHUNK) {
            const float* xn0 = Xr0 + (kt + 1) * BK;
            const float* xn1 = Xr1 + (kt + 1) * BK;
            ra0 = *(const float2*)(xn0);
            ra2 = *(const float2*)(xn0 + 8);
            ra1 = *(const float2*)(xn1);
            ra3 = *(const float2*)(xn1 + 8);
        }

        // compute: 8 n-tiles x 4 MMAs on this k16 slice
        const char* Bbase = smem + stage * WSTAGE_B;
#pragma unroll
        for (int nt = 0; nt < 8; nt++) {
            uint4 b = *(const uint4*)(Bbase + boff + nt * 512);
            mma_f16(acc[nt], ah1[0], ah1[1], ah1[2], ah1[3], b.x, b.y);  // h1*h1
            mma_f16(acc[nt], ah1[0], ah1[1], ah1[2], ah1[3], b.z, b.w);  // h1*h2
            mma_f16(acc[nt], ah2[0], ah2[1], ah2[2], ah2[3], b.x, b.y);  // h2*h1
            mma_f16(acc[nt], ah2[0], ah2[1], ah2[2], ah2[3], b.z, b.w);  // h2*h2
        }

        CP_WAIT0();
        __syncthreads();
    }

    // ---- epilogue: red[2][64][68] (k16-slice partials), unscale by 2^-18 ----
    float* red = (float*)smem;
#pragma unroll
    for (int nt = 0; nt < 8; nt++) {
        const int e = nt * 8 + 2 * tg;
        *(float2*)&red[(ksl * 64 + row0) * 68 + e] =
            make_float2(acc[nt][0] * UNSCALE, acc[nt][1] * UNSCALE);
        *(float2*)&red[(ksl * 64 + row0 + 8) * 68 + e] =
            make_float2(acc[nt][2] * UNSCALE, acc[nt][3] * UNSCALE);
    }
    __syncthreads();

    for (int i = tid; i < BM * NEXP; i += NTHREADS) {
        const int t = i >> 6, e = i & 63;
        red[t * 68 + e] = red[t * 68 + e] + red[(64 + t) * 68 + e];
    }
    __syncthreads();

    float* sc = red;   // [64][68]

    // ---- per-token softmax + top-2 ----
    if (tid < BM) {
        float v[64];
#pragma unroll
        for (int e = 0; e < NEXP; e++) v[e] = sc[tid * 68 + e];
        float mx = v[0];
#pragma unroll
        for (int e = 1; e < NEXP; e++) mx = fmaxf(mx, v[e]);
        float sum = 0.0f;
#pragma unroll
        for (int e = 0; e < NEXP; e++) { v[e] = expf(v[e] - mx); sum += v[e]; }
        float inv = 1.0f / sum;

        float v1 = -1.0f, v2 = -1.0f;
        int i1 = 0, i2 = 0;
#pragma unroll
        for (int e = 0; e < NEXP; e++) {
            float p = v[e] * inv;
            sc[tid * 68 + e] = p;
            if (p > v1) { v2 = v1; i2 = i1; v1 = p; i1 = e; }
            else if (p > v2) { v2 = p; i2 = e; }
        }
        float tot = v1 + v2 + 1e-20f;
        const int gt = tok0 + tid;
        out[2 * gt + 0] = (float)i1;
        out[2 * gt + 1] = (float)i2;
        out[2 * T_TOK + 2 * gt + 0] = v1 / tot;
        out[2 * T_TOK + 2 * gt + 1] = v2 / tot;

        atomicAdd(&cnt[i1], 1u);
        atomicAdd(&cnt[i2], 1u);
    }
    __syncthreads();

    // ---- per-expert sums -> global ----
    if (tid < NEXP) {
        float cs = 0.0f;
#pragma unroll 8
        for (int t = 0; t < BM; t++) cs += sc[t * 68 + tid];
        const int b = tok0 / SEQ;
        atomicAdd(&g_score_sum[b * NEXP + tid], cs);
        atomicAdd(&g_counts[b * NEXP + tid], cnt[tid]);
    }

    // ---- last-block finalize (aux loss) ----
    __threadfence();
    __syncthreads();
    if (tid == 0) {
        unsigned int v = atomicAdd(&g_done, 1u);
        last_flag = (v == (unsigned int)(GRID - 1));
    }
    __syncthreads();
    if (last_flag) {
        float* redf = (float*)smem;
        const int i = tid;            // 256 = NB*NEXP
        float sv = *((volatile float*)&g_score_sum[i]);
        unsigned int cv = *((volatile unsigned int*)&g_counts[i]);
        float v = (float)cv * ((float)NEXP / (float)(SEQ * 2)) * (sv / (float)SEQ);
        g_score_sum[i] = 0.0f;
        g_counts[i] = 0u;
        if (tid == 0) g_done = 0u;
        redf[i] = v;
        __syncthreads();
        for (int s = (NB * NEXP) / 2; s > 0; s >>= 1) {
            if (i < s) redf[i] += redf[i + s];
            __syncthreads();
        }
        if (i == 0) out[4 * T_TOK] = redf[0] * (0.1f / (float)NB);
    }
}

extern "C" void kernel_launch(void* const* d_in, const int* in_sizes, int n_in,
                              void* d_out, int out_size) {
    const float* X = (const float*)d_in[0];   // [4,4096,2048] f32
    const float* W = (const float*)d_in[1];   // [64,2048] f32
    float* out = (float*)d_out;

    presplit_w_kernel<<<NKB * NEXP * 4 / 256, 256>>>(W);
    cudaFuncSetAttribute(moe_gate_f16, cudaFuncAttributeMaxDynamicSharedMemorySize, SMEM_BYTES);
    moe_gate_f16<<<GRID, NTHREADS, SMEM_BYTES>>>(X, out);
}